// round 13
// baseline (speedup 1.0000x reference)
#include <cuda_runtime.h>
#include <cuda_fp16.h>
#include <math.h>
#include <stdint.h>

// ---------------- problem constants ----------------
#define B_SZ   1024
#define HID    512
#define INSZ   64
#define TSTEPS 256
#define GATES  2048              // 4*HID
#define KTOT   576               // INSZ + HID
#define XCOLS  (TSTEPS * INSZ)   // 16384

// ---------------- GEMM tiling ----------------
#define BM 128
#define BN 64                    // 2 CTAs per SM
#define KTILE 64                 // 64 fp16 = 128 bytes per row
#define NJOBS 9                  // job j = K-chunk j (0 = x, 1..8 = h)
#define NROWCTA 32               // CTAs per row group (same blockIdx.y)

// SW128 swizzle (Swizzle<3,4,3>) on byte offsets within a tile
#define SWZ(o) ((o) ^ (((o) >> 3) & 0x70))

// dynamic smem layout (all tile bases 1024-aligned)
#define SOFF_BH    0                         // 9 x 8192 = 73728 (resident W)
#define SOFF_A     73728                     // 2 x 16384 (double buffer)
#define SMEM_TOTAL (SOFF_A + 32768)          // 106496 (x2 CTAs = 212992)

// ---------------- device scratch (no allocs allowed) ----------------
static __device__ __align__(256) __half g_x[(size_t)B_SZ * XCOLS];   // fp16 x
static __device__ __align__(256) __half g_Bh[GATES * KTOT];          // fp16(W), packed col = n*4+g
static __device__ float  g_bias[GATES];
static __device__ __align__(256) __half g_h[2][B_SZ * HID];          // fp16 h (double buffer)
// per-row-group tickets, 128B apart; reset to 0 at the start of every launch
static __device__ unsigned long long g_row_ticket[8 * 16];

// ---------------- PTX helpers ----------------
__device__ __forceinline__ uint32_t smem_u32(const void* p) {
    uint32_t a;
    asm("{ .reg .u64 t; cvta.to.shared.u64 t, %1; cvt.u32.u64 %0, t; }"
        : "=r"(a) : "l"(p));
    return a;
}

__device__ __forceinline__ void cp16(uint32_t dst, const void* src) {
    asm volatile("cp.async.cg.shared.global [%0], [%1], 16;"
                 :: "r"(dst), "l"(src));
}
__device__ __forceinline__ void cp_commit() {
    asm volatile("cp.async.commit_group;" ::: "memory");
}
template<int N>
__device__ __forceinline__ void cp_wait() {
    asm volatile("cp.async.wait_group %0;" :: "n"(N) : "memory");
}

__device__ __forceinline__ void ldsm4(uint32_t* r, uint32_t addr) {
    asm volatile("ldmatrix.sync.aligned.m8n8.x4.shared.b16 {%0,%1,%2,%3}, [%4];"
                 : "=r"(r[0]), "=r"(r[1]), "=r"(r[2]), "=r"(r[3]) : "r"(addr));
}

__device__ __forceinline__ void mma16816(float* c, const uint32_t* a, const uint32_t* b) {
    asm volatile(
        "mma.sync.aligned.m16n8k16.row.col.f32.f16.f16.f32 "
        "{%0,%1,%2,%3}, {%4,%5,%6,%7}, {%8,%9}, {%0,%1,%2,%3};"
        : "+f"(c[0]), "+f"(c[1]), "+f"(c[2]), "+f"(c[3])
        : "r"(a[0]), "r"(a[1]), "r"(a[2]), "r"(a[3]), "r"(b[0]), "r"(b[1]));
}

__device__ __forceinline__ float fsig(float x) {
    float e = __expf(-x);
    return __fdividef(1.f, 1.f + e);
}
__device__ __forceinline__ float ftanh(float x) {
    return 2.f * fsig(2.f * x) - 1.f;
}

// ---------------- prepack kernels ----------------
__global__ void prepack_x_kernel(const float* __restrict__ x) {
    size_t idx = (size_t)blockIdx.x * blockDim.x + threadIdx.x;
    size_t stride = (size_t)gridDim.x * blockDim.x;
    const size_t total = (size_t)B_SZ * XCOLS;
    for (size_t i = idx; i < total; i += stride)
        g_x[i] = __float2half_rn(x[i]);
}

__global__ void prepack_w_kernel(const float* __restrict__ W_ih,
                                 const float* __restrict__ W_hh,
                                 const float* __restrict__ b_ih,
                                 const float* __restrict__ b_hh) {
    int idx = blockIdx.x * blockDim.x + threadIdx.x;
    int stride = gridDim.x * blockDim.x;
    const int total = GATES * KTOT;
    for (int i = idx; i < total; i += stride) {
        int col = i / KTOT;
        int k   = i - col * KTOT;
        int n = col >> 2, g = col & 3;
        int row = g * HID + n;
        float v = (k < INSZ) ? W_ih[row * INSZ + k] : W_hh[row * HID + (k - INSZ)];
        g_Bh[i] = __float2half_rn(v);
    }
    for (int i = idx; i < GATES; i += stride) {
        int n = i >> 2, g = i & 3;
        int row = g * HID + n;
        g_bias[i] = b_ih[row] + b_hh[row];
    }
}

// init h0 (fp16) + reset row tickets, folded into one launch
__global__ void init_state_kernel(const float* __restrict__ h0) {
    int idx = blockIdx.x * blockDim.x + threadIdx.x;
    int stride = gridDim.x * blockDim.x;
    for (int i = idx; i < B_SZ * HID; i += stride)
        g_h[0][i] = __float2half_rn(h0[i]);
    if (blockIdx.x == 0 && threadIdx.x < 8 * 16)
        g_row_ticket[threadIdx.x] = 0ULL;
}

// ---------------- persistent LSTM kernel (256 threads, 2 CTAs/SM) ----------------
// A tiles are DOUBLE buffered with global alternation:
//   x(t) -> buf t&1, h_j(t) -> buf (t+j)&1.
// Therefore lookahead is strictly 1: at job j's sync point, the only free
// buffer is (t+j+1)&1 (last read by job j-1, fenced by the __syncthreads).
__global__ __launch_bounds__(256, 2)
void lstm_persistent(const float* __restrict__ c0g)
{
    extern __shared__ char smem[];
    const uint32_t sbase = smem_u32(smem);
    const int tid  = threadIdx.x;
    const int wid  = tid >> 5;
    const int lane = tid & 31;
    const int row0 = blockIdx.y * BM;   // batch base
    const int col0 = blockIdx.x * BN;   // packed gate col base
    const int wm = wid & 3;             // 0..3 (M, 32 rows each)
    const int wn = wid >> 2;            // 0..1 (N, 32 cols each)

    // ---- load resident W (9 chunks of 64 gate-cols x 64 K, 72KB) ----
    {
        const int r2    = tid >> 2;           // 0..63 (B row = packed gate col)
        const int quart = tid & 3;            // 16-elem group
        const uint32_t rowoff2 = (uint32_t)r2 * 128 + (uint32_t)quart * 32;
        const size_t bb = (size_t)(col0 + r2) * KTOT + (size_t)quart * 16;
        for (int sub = 0; sub < 9; ++sub) {
            uint32_t dst = sbase + SOFF_BH + sub * 8192;
#pragma unroll
            for (int c = 0; c < 2; ++c)
                cp16(dst + SWZ(rowoff2 + c * 16), g_Bh + bb + sub * KTILE + c * 8);
        }
        cp_commit();
    }

    // A-tile loader mapping: 256 threads cover 128 rows x 128B (64B per thread)
    const int r     = tid >> 1;
    const int halfe = (tid & 1) * 32;              // element offset
    const uint32_t rowoff = (uint32_t)r * 128 + (tid & 1) * 64;

    // ---- per-thread epilogue constants: c state + bias in registers ----
    const int q  = lane & 3;
    const bool ev = (q & 1) == 0;
    float creg[2][4][2];
    float bb0[4], bb1[4];
#pragma unroll
    for (int nf = 0; nf < 4; ++nf) {
        int cb = wn * 32 + nf * 8 + q * 2;
        bb0[nf] = g_bias[col0 + cb];
        bb1[nf] = g_bias[col0 + cb + 1];
#pragma unroll
        for (int mf = 0; mf < 2; ++mf)
#pragma unroll
            for (int rs = 0; rs < 2; ++rs) {
                int n = (col0 + cb) >> 2;
                int b = row0 + wm * 32 + (lane >> 2) + mf * 16 + rs * 8;
                creg[mf][nf][rs] = c0g[(size_t)b * HID + n];
            }
    }

    // fragment addressing constants
    const int lane7 = lane & 7;
    const int arow  = wm * 32 + ((lane >> 3) & 1) * 8 + lane7;   // + mf*16
    const int ach   = (lane >> 4) & 1;
    const int brow  = wn * 32 + ((lane >> 4) & 1) * 8 + lane7;   // + p*16
    const int bch   = (lane >> 3) & 1;

    const uint32_t sA0 = sbase + SOFF_A;

    auto issue_x = [&](int t) {
        const size_t abase = (size_t)(row0 + r) * XCOLS + (size_t)t * INSZ
                             + (size_t)halfe;
        const uint32_t ao = (uint32_t)(t & 1) * 16384;
#pragma unroll
        for (int c = 0; c < 4; ++c)
            cp16(sA0 + ao + SWZ(rowoff + c * 16), g_x + abase + c * 8);
        cp_commit();
    };
    auto issue_h = [&](int jid, int t, int buf) {
        const size_t abase = (size_t)(row0 + r) * HID + (size_t)(jid - 1) * KTILE
                             + (size_t)halfe;
        const uint32_t ao = (uint32_t)((t + jid) & 1) * 16384;
#pragma unroll
        for (int c = 0; c < 4; ++c)
            cp16(sA0 + ao + SWZ(rowoff + c * 16), g_h[buf] + abase + c * 8);
        cp_commit();
    };

    float acc[2][4][4];

    // MMA of one job: 4 kk slices against resident W chunk j, A in buffer abuf
    auto mma_job = [&](int j, uint32_t abuf) {
        const uint32_t sA  = sA0 + abuf * 16384;
        const uint32_t sBH = sbase + SOFF_BH + (uint32_t)j * 8192;
#pragma unroll
        for (int kk = 0; kk < 4; ++kk) {
            uint32_t af[2][4];
#pragma unroll
            for (int mf = 0; mf < 2; ++mf)
                ldsm4(af[mf], sA + SWZ((uint32_t)(arow + mf * 16) * 128
                                       + (uint32_t)(kk * 2 + ach) * 16));
            uint32_t bf[4][2];
#pragma unroll
            for (int p = 0; p < 2; ++p) {
                uint32_t rr[4];
                ldsm4(rr, sBH + SWZ((uint32_t)(brow + p * 16) * 128
                                    + (uint32_t)(kk * 2 + bch) * 16));
                bf[p * 2 + 0][0] = rr[0]; bf[p * 2 + 0][1] = rr[1];
                bf[p * 2 + 1][0] = rr[2]; bf[p * 2 + 1][1] = rr[3];
            }
#pragma unroll
            for (int mf = 0; mf < 2; ++mf)
#pragma unroll
                for (int nf = 0; nf < 4; ++nf)
                    mma16816(acc[mf][nf], af[mf], bf[nf]);
        }
    };

    // prologue: x job of step 0 (after W group)
    issue_x(0);

    for (int t = 0; t < TSTEPS; ++t) {
        const int buf  = t & 1;
        const int nbuf = buf ^ 1;

#pragma unroll
        for (int mf = 0; mf < 2; ++mf)
#pragma unroll
            for (int nf = 0; nf < 4; ++nf)
#pragma unroll
                for (int u = 0; u < 4; ++u) acc[mf][nf][u] = 0.f;

        // ---- job 0 (x): barrier-independent, hides the row-group spin ----
        cp_wait<0>();           // x tile (and W at t=0) resident
        __syncthreads();
        mma_job(0, (uint32_t)(t & 1));

        // ---- row-group barrier: h[t] visible (overlapped by job-0 MMA) ----
        if (t > 0 && tid == 0) {
            const unsigned long long target =
                (unsigned long long)t * (unsigned long long)NROWCTA;
            unsigned long long cur;
            unsigned long long* p = &g_row_ticket[blockIdx.y * 16];
            do {
                asm volatile("ld.acquire.gpu.u64 %0, [%1];" : "=l"(cur) : "l"(p));
            } while (cur < target);
        }
        __syncthreads();   // all warps past job-0 MMA; h[t] visible

        // h safe to read; buffer (t+1)&1 free (last read two steps ago)
        issue_h(1, t, buf);

        // ---- jobs 1..8: strict lookahead-1 (double buffer) ----
        for (int j = 1; j < NJOBS; ++j) {
            cp_wait<0>();       // job j's tile arrived
            __syncthreads();    // all warps past job j-1 -> buffer (t+j+1)&1 free
            if (j + 1 < NJOBS) {
                issue_h(j + 1, t, buf);
            } else if (t + 1 < TSTEPS) {
                issue_x(t + 1);           // buf (t+1)&1, freed by job j-1=7
            }
            mma_job(j, (uint32_t)((t + j) & 1));
        }

        // ---- fused LSTM epilogue ----
#pragma unroll
        for (int mf = 0; mf < 2; ++mf) {
#pragma unroll
            for (int nf = 0; nf < 4; ++nf) {
                const int cb = wn * 32 + nf * 8 + q * 2;
#pragma unroll
                for (int rs = 0; rs < 2; ++rs) {
                    float v0 = acc[mf][nf][rs * 2 + 0] + bb0[nf];
                    float v1 = acc[mf][nf][rs * 2 + 1] + bb1[nf];
                    // even lanes: x0=sig(i), x1=sig(f); odd: x0=tanh(g), x1=sig(o)
                    float x0 = ev ? fsig(v0) : ftanh(v0);
                    float x1 = fsig(v1);
                    float y0 = __shfl_xor_sync(0xffffffffu, x0, 1);
                    float y1 = __shfl_xor_sync(0xffffffffu, x1, 1);
                    if (ev) {
                        const int n = (col0 + cb) >> 2;
                        const int b = row0 + wm * 32 + (lane >> 2) + mf * 16 + rs * 8;
                        const size_t idx = (size_t)b * HID + n;
                        float cn = x1 * creg[mf][nf][rs] + x0 * y0;   // f*c + i*g
                        creg[mf][nf][rs] = cn;
                        float hn = y1 * ftanh(cn);                    // o * tanh(c)
                        g_h[nbuf][idx] = __float2half_rn(hn);
                    }
                }
            }
        }

        // post arrival for next step's row barrier (release semantics)
        if (t + 1 < TSTEPS) {
            __syncthreads();   // h stores complete block-wide
            if (tid == 0) {
                unsigned long long one = 1ULL;
                asm volatile("red.release.gpu.global.add.u64 [%0], %1;"
                             :: "l"(&g_row_ticket[blockIdx.y * 16]), "l"(one)
                             : "memory");
            }
        }
    }
}

// ---------------- final linear ----------------
__global__ void final_linear_kernel(const float* __restrict__ W_lin,
                                    const float* __restrict__ b_lin,
                                    float* __restrict__ out, int buf)
{
    int b = blockIdx.x;
    int w = threadIdx.y;      // 0..9
    int lane = threadIdx.x;   // 0..31
    const __half* h = g_h[buf] + (size_t)b * HID;
    const float* wl = W_lin + (size_t)w * HID;
    float s = 0.f;
#pragma unroll 4
    for (int k = lane; k < HID; k += 32)
        s += __half2float(h[k]) * wl[k];
#pragma unroll
    for (int off = 16; off; off >>= 1)
        s += __shfl_down_sync(0xffffffffu, s, off);
    if (lane == 0)
        out[b * 10 + w] = s + b_lin[w];
}

// ---------------- launch ----------------
extern "C" void kernel_launch(void* const* d_in, const int* in_sizes, int n_in,
                              void* d_out, int out_size)
{
    const float* x     = (const float*)d_in[0];
    const float* h0    = (const float*)d_in[1];
    const float* c0    = (const float*)d_in[2];
    const float* W_ih  = (const float*)d_in[3];
    const float* W_hh  = (const float*)d_in[4];
    const float* b_ih  = (const float*)d_in[5];
    const float* b_hh  = (const float*)d_in[6];
    const float* W_lin = (const float*)d_in[7];
    const float* b_lin = (const float*)d_in[8];
    float* out = (float*)d_out;

    cudaFuncSetAttribute(lstm_persistent,
                         cudaFuncAttributeMaxDynamicSharedMemorySize, SMEM_TOTAL);

    prepack_x_kernel<<<2048, 256>>>(x);
    prepack_w_kernel<<<1024, 256>>>(W_ih, W_hh, b_ih, b_hh);
    init_state_kernel<<<512, 512>>>(h0);

    dim3 grid(GATES / BN, B_SZ / BM);   // 32 x 8 = 256 CTAs, 2 per SM
    lstm_persistent<<<grid, 256, SMEM_TOTAL>>>(c0);

    // 256 steps -> final h is in buffer 0
    final_linear_kernel<<<B_SZ, dim3(32, 10)>>>(W_lin, b_lin, out, 0);
}

// round 14
// speedup vs baseline: 1.1711x; 1.1711x over previous
#include <cuda_runtime.h>
#include <cuda_fp16.h>
#include <math.h>
#include <stdint.h>

// ---------------- problem constants ----------------
#define B_SZ   1024
#define HID    512
#define INSZ   64
#define TSTEPS 256
#define GATES  2048              // 4*HID
#define KTOT   576               // INSZ + HID
#define XCOLS  (TSTEPS * INSZ)   // 16384

// ---------------- GEMM tiling ----------------
#define BM 128
#define BN 128
#define KTILE 64                 // 64 fp16 = 128 bytes per row
#define NJOBS 5                  // job 0 = x (1 chunk), jobs 1..4 = 2 h-chunks each
#define NROWCTA 16               // CTAs per row group (same blockIdx.y)

// SW128 swizzle (Swizzle<3,4,3>) on byte offsets within a tile
#define SWZ(o) ((o) ^ (((o) >> 3) & 0x70))

// dynamic smem layout (all tile bases 1024-aligned)
#define SOFF_BH    0                         // 9 x 16384 = 147456 (resident W)
#define SOFF_A     147456                    // 2 x 32768 (double buffer, 2 sub-tiles each)
#define SMEM_TOTAL (SOFF_A + 65536)          // 212992

// ---------------- device scratch (no allocs allowed) ----------------
static __device__ __align__(256) __half g_x[(size_t)B_SZ * XCOLS];   // fp16 x
static __device__ __align__(256) __half g_Bh[GATES * KTOT];          // fp16(W), packed col = n*4+g
static __device__ float  g_bias[GATES];
static __device__ __align__(256) __half g_h[2][B_SZ * HID];          // fp16 h (double buffer)
// per-row-group tickets, 128B apart; reset to 0 at the start of every launch
static __device__ unsigned long long g_row_ticket[8 * 16];

// ---------------- PTX helpers ----------------
__device__ __forceinline__ uint32_t smem_u32(const void* p) {
    uint32_t a;
    asm("{ .reg .u64 t; cvta.to.shared.u64 t, %1; cvt.u32.u64 %0, t; }"
        : "=r"(a) : "l"(p));
    return a;
}

__device__ __forceinline__ void cp16(uint32_t dst, const void* src) {
    asm volatile("cp.async.cg.shared.global [%0], [%1], 16;"
                 :: "r"(dst), "l"(src));
}
__device__ __forceinline__ void cp_commit() {
    asm volatile("cp.async.commit_group;" ::: "memory");
}
template<int N>
__device__ __forceinline__ void cp_wait() {
    asm volatile("cp.async.wait_group %0;" :: "n"(N) : "memory");
}

__device__ __forceinline__ void ldsm4(uint32_t* r, uint32_t addr) {
    asm volatile("ldmatrix.sync.aligned.m8n8.x4.shared.b16 {%0,%1,%2,%3}, [%4];"
                 : "=r"(r[0]), "=r"(r[1]), "=r"(r[2]), "=r"(r[3]) : "r"(addr));
}

__device__ __forceinline__ void mma16816(float* c, const uint32_t* a, const uint32_t* b) {
    asm volatile(
        "mma.sync.aligned.m16n8k16.row.col.f32.f16.f16.f32 "
        "{%0,%1,%2,%3}, {%4,%5,%6,%7}, {%8,%9}, {%0,%1,%2,%3};"
        : "+f"(c[0]), "+f"(c[1]), "+f"(c[2]), "+f"(c[3])
        : "r"(a[0]), "r"(a[1]), "r"(a[2]), "r"(a[3]), "r"(b[0]), "r"(b[1]));
}

__device__ __forceinline__ float fsig(float x) {
    float e = __expf(-x);
    return __fdividef(1.f, 1.f + e);
}
__device__ __forceinline__ float ftanh(float x) {
    return 2.f * fsig(2.f * x) - 1.f;
}

// ---------------- prepack kernels ----------------
__global__ void prepack_x_kernel(const float* __restrict__ x) {
    size_t idx = (size_t)blockIdx.x * blockDim.x + threadIdx.x;
    size_t stride = (size_t)gridDim.x * blockDim.x;
    const size_t total = (size_t)B_SZ * XCOLS;
    for (size_t i = idx; i < total; i += stride)
        g_x[i] = __float2half_rn(x[i]);
}

__global__ void prepack_w_kernel(const float* __restrict__ W_ih,
                                 const float* __restrict__ W_hh,
                                 const float* __restrict__ b_ih,
                                 const float* __restrict__ b_hh) {
    int idx = blockIdx.x * blockDim.x + threadIdx.x;
    int stride = gridDim.x * blockDim.x;
    const int total = GATES * KTOT;
    for (int i = idx; i < total; i += stride) {
        int col = i / KTOT;
        int k   = i - col * KTOT;
        int n = col >> 2, g = col & 3;
        int row = g * HID + n;
        float v = (k < INSZ) ? W_ih[row * INSZ + k] : W_hh[row * HID + (k - INSZ)];
        g_Bh[i] = __float2half_rn(v);
    }
    for (int i = idx; i < GATES; i += stride) {
        int n = i >> 2, g = i & 3;
        int row = g * HID + n;
        g_bias[i] = b_ih[row] + b_hh[row];
    }
}

// init h0 (fp16) + reset row tickets, folded into one launch
__global__ void init_state_kernel(const float* __restrict__ h0) {
    int idx = blockIdx.x * blockDim.x + threadIdx.x;
    int stride = gridDim.x * blockDim.x;
    for (int i = idx; i < B_SZ * HID; i += stride)
        g_h[0][i] = __float2half_rn(h0[i]);
    if (blockIdx.x == 0 && threadIdx.x < 8 * 16)
        g_row_ticket[threadIdx.x] = 0ULL;
}

// ---------------- persistent LSTM kernel (512 threads) ----------------
// 5 jobs per step over a 2x32KB A double buffer; buffer of job j at step t is
// (t+j)&1 (5 jobs/step keeps global parity alternating). Lookahead is strictly
// 1: job j+1's buffer equals job j-1's, freed by the preceding __syncthreads.
__global__ __launch_bounds__(512, 1)
void lstm_persistent(const float* __restrict__ c0g)
{
    extern __shared__ char smem[];
    const uint32_t sbase = smem_u32(smem);
    const int tid  = threadIdx.x;
    const int wid  = tid >> 5;
    const int lane = tid & 31;
    const int row0 = blockIdx.y * BM;   // batch base
    const int col0 = blockIdx.x * BN;   // packed gate col base
    const int wm = wid & 3;             // 0..3 (M, 32 rows each)
    const int wn = wid >> 2;            // 0..3 (N, 32 cols each)

    // loader mapping: 512 threads cover 128 rows x 128B (32B per thread)
    const int r     = tid >> 2;
    const int quart = tid & 3;
    const uint32_t rowoff = (uint32_t)r * 128 + (uint32_t)quart * 32;

    // ---- load resident W (9 chunks, 147KB) ----
    {
        const size_t bb = (size_t)(col0 + r) * KTOT + (size_t)quart * 16;
        for (int sub = 0; sub < 9; ++sub) {
            uint32_t dst = sbase + SOFF_BH + sub * 16384;
#pragma unroll
            for (int c = 0; c < 2; ++c)
                cp16(dst + SWZ(rowoff + c * 16), g_Bh + bb + sub * KTILE + c * 8);
        }
        cp_commit();
    }

    // ---- per-thread epilogue constants: c state + bias in registers ----
    const int q  = lane & 3;
    const bool ev = (q & 1) == 0;
    float creg[2][4][2];
    float bb0[4], bb1[4];
#pragma unroll
    for (int nf = 0; nf < 4; ++nf) {
        int cb = wn * 32 + nf * 8 + q * 2;
        bb0[nf] = g_bias[col0 + cb];
        bb1[nf] = g_bias[col0 + cb + 1];
#pragma unroll
        for (int mf = 0; mf < 2; ++mf)
#pragma unroll
            for (int rs = 0; rs < 2; ++rs) {
                int n = (col0 + cb) >> 2;
                int b = row0 + wm * 32 + (lane >> 2) + mf * 16 + rs * 8;
                creg[mf][nf][rs] = c0g[(size_t)b * HID + n];
            }
    }

    // fragment addressing constants
    const int lane7 = lane & 7;
    const int arow  = wm * 32 + ((lane >> 3) & 1) * 8 + lane7;   // + mf*16
    const int ach   = (lane >> 4) & 1;
    const int brow  = wn * 32 + ((lane >> 4) & 1) * 8 + lane7;   // + p*16
    const int bch   = (lane >> 3) & 1;

    const uint32_t sA0 = sbase + SOFF_A;

    // ---- loads ----
    // x job: chunk 0 -> sub-tile 0 of buffer abuf (16KB)
    auto issue_x = [&](int t, uint32_t abuf) {
        const size_t abase = (size_t)(row0 + r) * XCOLS + (size_t)t * INSZ
                             + (size_t)quart * 16;
        const uint32_t ao = abuf * 32768;
#pragma unroll
        for (int c = 0; c < 2; ++c)
            cp16(sA0 + ao + SWZ(rowoff + c * 16), g_x + abase + c * 8);
        cp_commit();
    };
    // h job j (1..4): chunks 2j-1, 2j -> sub-tiles 0,1 of buffer abuf (32KB)
    auto issue_h2 = [&](int jid, int buf, uint32_t abuf) {
        const uint32_t ao = abuf * 32768;
        const size_t hbase = (size_t)(row0 + r) * HID + (size_t)quart * 16;
#pragma unroll
        for (int s = 0; s < 2; ++s) {
            const size_t abase = hbase + (size_t)(2 * jid - 2 + s) * KTILE;
#pragma unroll
            for (int c = 0; c < 2; ++c)
                cp16(sA0 + ao + (uint32_t)s * 16384 + SWZ(rowoff + c * 16),
                     g_h[buf] + abase + c * 8);
        }
        cp_commit();
    };

    float acc[2][4][4];

    // MMA of one 16KB sub-tile against resident W chunk
    auto mma_chunk = [&](uint32_t sA, int chunk) {
        const uint32_t sBH = sbase + SOFF_BH + (uint32_t)chunk * 16384;
#pragma unroll
        for (int kk = 0; kk < 4; ++kk) {
            uint32_t af[2][4];
#pragma unroll
            for (int mf = 0; mf < 2; ++mf)
                ldsm4(af[mf], sA + SWZ((uint32_t)(arow + mf * 16) * 128
                                       + (uint32_t)(kk * 2 + ach) * 16));
            uint32_t bf[4][2];
#pragma unroll
            for (int p = 0; p < 2; ++p) {
                uint32_t rr[4];
                ldsm4(rr, sBH + SWZ((uint32_t)(brow + p * 16) * 128
                                    + (uint32_t)(kk * 2 + bch) * 16));
                bf[p * 2 + 0][0] = rr[0]; bf[p * 2 + 0][1] = rr[1];
                bf[p * 2 + 1][0] = rr[2]; bf[p * 2 + 1][1] = rr[3];
            }
#pragma unroll
            for (int mf = 0; mf < 2; ++mf)
#pragma unroll
                for (int nf = 0; nf < 4; ++nf)
                    mma16816(acc[mf][nf], af[mf], bf[nf]);
        }
    };

    // prologue: x job of step 0 into buffer (0+0)&1 = 0
    issue_x(0, 0);

    for (int t = 0; t < TSTEPS; ++t) {
        const int buf  = t & 1;
        const int nbuf = buf ^ 1;

#pragma unroll
        for (int mf = 0; mf < 2; ++mf)
#pragma unroll
            for (int nf = 0; nf < 4; ++nf)
#pragma unroll
                for (int u = 0; u < 4; ++u) acc[mf][nf][u] = 0.f;

        // ---- job 0 (x): barrier-independent, hides the row-group spin ----
        cp_wait<0>();           // x tile (and W at t=0) resident
        __syncthreads();
        mma_chunk(sA0 + (uint32_t)(t & 1) * 32768, 0);

        // ---- row-group barrier: h[t] visible (overlapped by job-0 MMA) ----
        if (t > 0 && tid == 0) {
            const unsigned long long target =
                (unsigned long long)t * (unsigned long long)NROWCTA;
            unsigned long long cur;
            unsigned long long* p = &g_row_ticket[blockIdx.y * 16];
            do {
                asm volatile("ld.acquire.gpu.u64 %0, [%1];" : "=l"(cur) : "l"(p));
            } while (cur < target);
        }
        __syncthreads();   // all warps past job-0 MMA; h[t] visible

        // h safe to read; buffer (t+1)&1 free (last read by step t-1's job 4)
        issue_h2(1, buf, (uint32_t)((t + 1) & 1));

        // ---- jobs 1..4: strict lookahead-1 (double buffer) ----
        for (int j = 1; j < NJOBS; ++j) {
            cp_wait<0>();       // job j's tiles arrived
            __syncthreads();    // all warps past job j-1 -> its buffer free
            if (j + 1 < NJOBS) {
                issue_h2(j + 1, buf, (uint32_t)((t + j + 1) & 1));
            } else if (t + 1 < TSTEPS) {
                issue_x(t + 1, (uint32_t)((t + 1) & 1));  // = (t+j+1)&1 at j=4
            }
            const uint32_t sAb = sA0 + (uint32_t)((t + j) & 1) * 32768;
            mma_chunk(sAb,         2 * j - 1);
            mma_chunk(sAb + 16384, 2 * j);
        }

        // ---- fused LSTM epilogue ----
#pragma unroll
        for (int mf = 0; mf < 2; ++mf) {
#pragma unroll
            for (int nf = 0; nf < 4; ++nf) {
                const int cb = wn * 32 + nf * 8 + q * 2;
#pragma unroll
                for (int rs = 0; rs < 2; ++rs) {
                    float v0 = acc[mf][nf][rs * 2 + 0] + bb0[nf];
                    float v1 = acc[mf][nf][rs * 2 + 1] + bb1[nf];
                    // even lanes: x0=sig(i), x1=sig(f); odd: x0=tanh(g), x1=sig(o)
                    float x0 = ev ? fsig(v0) : ftanh(v0);
                    float x1 = fsig(v1);
                    float y0 = __shfl_xor_sync(0xffffffffu, x0, 1);
                    float y1 = __shfl_xor_sync(0xffffffffu, x1, 1);
                    if (ev) {
                        const int n = (col0 + cb) >> 2;
                        const int b = row0 + wm * 32 + (lane >> 2) + mf * 16 + rs * 8;
                        const size_t idx = (size_t)b * HID + n;
                        float cn = x1 * creg[mf][nf][rs] + x0 * y0;   // f*c + i*g
                        creg[mf][nf][rs] = cn;
                        float hn = y1 * ftanh(cn);                    // o * tanh(c)
                        g_h[nbuf][idx] = __float2half_rn(hn);
                    }
                }
            }
        }

        // post arrival for next step's row barrier (release semantics)
        if (t + 1 < TSTEPS) {
            __syncthreads();   // h stores complete block-wide
            if (tid == 0) {
                unsigned long long one = 1ULL;
                asm volatile("red.release.gpu.global.add.u64 [%0], %1;"
                             :: "l"(&g_row_ticket[blockIdx.y * 16]), "l"(one)
                             : "memory");
            }
        }
    }
}

// ---------------- final linear ----------------
__global__ void final_linear_kernel(const float* __restrict__ W_lin,
                                    const float* __restrict__ b_lin,
                                    float* __restrict__ out, int buf)
{
    int b = blockIdx.x;
    int w = threadIdx.y;      // 0..9
    int lane = threadIdx.x;   // 0..31
    const __half* h = g_h[buf] + (size_t)b * HID;
    const float* wl = W_lin + (size_t)w * HID;
    float s = 0.f;
#pragma unroll 4
    for (int k = lane; k < HID; k += 32)
        s += __half2float(h[k]) * wl[k];
#pragma unroll
    for (int off = 16; off; off >>= 1)
        s += __shfl_down_sync(0xffffffffu, s, off);
    if (lane == 0)
        out[b * 10 + w] = s + b_lin[w];
}

// ---------------- launch ----------------
extern "C" void kernel_launch(void* const* d_in, const int* in_sizes, int n_in,
                              void* d_out, int out_size)
{
    const float* x     = (const float*)d_in[0];
    const float* h0    = (const float*)d_in[1];
    const float* c0    = (const float*)d_in[2];
    const float* W_ih  = (const float*)d_in[3];
    const float* W_hh  = (const float*)d_in[4];
    const float* b_ih  = (const float*)d_in[5];
    const float* b_hh  = (const float*)d_in[6];
    const float* W_lin = (const float*)d_in[7];
    const float* b_lin = (const float*)d_in[8];
    float* out = (float*)d_out;

    cudaFuncSetAttribute(lstm_persistent,
                         cudaFuncAttributeMaxDynamicSharedMemorySize, SMEM_TOTAL);

    prepack_x_kernel<<<2048, 256>>>(x);
    prepack_w_kernel<<<1024, 256>>>(W_ih, W_hh, b_ih, b_hh);
    init_state_kernel<<<512, 512>>>(h0);

    dim3 grid(GATES / BN, B_SZ / BM);   // 16 x 8 = 128 CTAs (all resident)
    lstm_persistent<<<grid, 512, SMEM_TOTAL>>>(c0);

    // 256 steps -> final h is in buffer 0
    final_linear_kernel<<<B_SZ, dim3(32, 10)>>>(W_lin, b_lin, out, 0);
}

// round 15
// speedup vs baseline: 1.3659x; 1.1663x over previous
#include <cuda_runtime.h>
#include <cuda_fp16.h>
#include <math.h>
#include <stdint.h>

// ---------------- problem constants ----------------
#define B_SZ   1024
#define HID    512
#define INSZ   64
#define TSTEPS 256
#define GATES  2048              // 4*HID
#define KTOT   576               // INSZ + HID
#define XCOLS  (TSTEPS * INSZ)   // 16384

// ---------------- GEMM tiling ----------------
#define BM 128
#define BN 128
#define KTILE 64                 // 64 fp16 = 128 bytes per row
#define NJOBS 9                  // job j = K-chunk j (0 = x, 1..8 = h)
#define NROWCTA 16               // CTAs per row group (same blockIdx.y)

// SW128 swizzle (Swizzle<3,4,3>) on byte offsets within a tile
#define SWZ(o) ((o) ^ (((o) >> 3) & 0x70))

// dynamic smem layout (all tile bases 1024-aligned)
#define SOFF_BH    0                         // 9 x 16384 = 147456 (resident W)
#define SOFF_A     147456                    // 3 x 16384 (triple buffer)
#define SMEM_TOTAL (SOFF_A + 49152)          // 196608

// ---------------- device scratch (no allocs allowed) ----------------
static __device__ __align__(256) __half g_x[(size_t)B_SZ * XCOLS];   // fp16 x
static __device__ __align__(256) __half g_Bh[GATES * KTOT];          // fp16(W), packed col = n*4+g
static __device__ float  g_bias[GATES];
static __device__ __align__(256) __half g_h[2][B_SZ * HID];          // fp16 h (double buffer)
// per-row-group tickets, 128B apart; reset to 0 at the start of every launch
static __device__ unsigned long long g_row_ticket[8 * 16];

// ---------------- PTX helpers ----------------
__device__ __forceinline__ uint32_t smem_u32(const void* p) {
    uint32_t a;
    asm("{ .reg .u64 t; cvta.to.shared.u64 t, %1; cvt.u32.u64 %0, t; }"
        : "=r"(a) : "l"(p));
    return a;
}

__device__ __forceinline__ void cp16(uint32_t dst, const void* src) {
    asm volatile("cp.async.cg.shared.global [%0], [%1], 16;"
                 :: "r"(dst), "l"(src));
}
__device__ __forceinline__ void cp_commit() {
    asm volatile("cp.async.commit_group;" ::: "memory");
}
template<int N>
__device__ __forceinline__ void cp_wait() {
    asm volatile("cp.async.wait_group %0;" :: "n"(N) : "memory");
}

__device__ __forceinline__ void ldsm4(uint32_t* r, uint32_t addr) {
    asm volatile("ldmatrix.sync.aligned.m8n8.x4.shared.b16 {%0,%1,%2,%3}, [%4];"
                 : "=r"(r[0]), "=r"(r[1]), "=r"(r[2]), "=r"(r[3]) : "r"(addr));
}

__device__ __forceinline__ void mma16816(float* c, const uint32_t* a, const uint32_t* b) {
    asm volatile(
        "mma.sync.aligned.m16n8k16.row.col.f32.f16.f16.f32 "
        "{%0,%1,%2,%3}, {%4,%5,%6,%7}, {%8,%9}, {%0,%1,%2,%3};"
        : "+f"(c[0]), "+f"(c[1]), "+f"(c[2]), "+f"(c[3])
        : "r"(a[0]), "r"(a[1]), "r"(a[2]), "r"(a[3]), "r"(b[0]), "r"(b[1]));
}

// hardware tanh (sm_75+): 1 MUFU op, |err| ~ 5e-4
__device__ __forceinline__ float ftanh(float x) {
    float y;
    asm("tanh.approx.f32 %0, %1;" : "=f"(y) : "f"(x));
    return y;
}
// sigmoid via hw tanh: sig(x) = 0.5 + 0.5*tanh(x/2)  (1 MUFU + 2 FMA)
__device__ __forceinline__ float fsig(float x) {
    return fmaf(0.5f, ftanh(0.5f * x), 0.5f);
}

// ---------------- prepack kernels ----------------
__global__ void prepack_x_kernel(const float* __restrict__ x) {
    size_t idx = (size_t)blockIdx.x * blockDim.x + threadIdx.x;
    size_t stride = (size_t)gridDim.x * blockDim.x;
    const size_t total = (size_t)B_SZ * XCOLS;
    for (size_t i = idx; i < total; i += stride)
        g_x[i] = __float2half_rn(x[i]);
}

__global__ void prepack_w_kernel(const float* __restrict__ W_ih,
                                 const float* __restrict__ W_hh,
                                 const float* __restrict__ b_ih,
                                 const float* __restrict__ b_hh) {
    int idx = blockIdx.x * blockDim.x + threadIdx.x;
    int stride = gridDim.x * blockDim.x;
    const int total = GATES * KTOT;
    for (int i = idx; i < total; i += stride) {
        int col = i / KTOT;
        int k   = i - col * KTOT;
        int n = col >> 2, g = col & 3;
        int row = g * HID + n;
        float v = (k < INSZ) ? W_ih[row * INSZ + k] : W_hh[row * HID + (k - INSZ)];
        g_Bh[i] = __float2half_rn(v);
    }
    for (int i = idx; i < GATES; i += stride) {
        int n = i >> 2, g = i & 3;
        int row = g * HID + n;
        g_bias[i] = b_ih[row] + b_hh[row];
    }
}

// init h0 (fp16) + reset row tickets, folded into one launch
__global__ void init_state_kernel(const float* __restrict__ h0) {
    int idx = blockIdx.x * blockDim.x + threadIdx.x;
    int stride = gridDim.x * blockDim.x;
    for (int i = idx; i < B_SZ * HID; i += stride)
        g_h[0][i] = __float2half_rn(h0[i]);
    if (blockIdx.x == 0 && threadIdx.x < 8 * 16)
        g_row_ticket[threadIdx.x] = 0ULL;
}

// ---------------- persistent LSTM kernel (512 threads) ----------------
__global__ __launch_bounds__(512, 1)
void lstm_persistent(const float* __restrict__ c0g)
{
    extern __shared__ char smem[];
    const uint32_t sbase = smem_u32(smem);
    const int tid  = threadIdx.x;
    const int wid  = tid >> 5;
    const int lane = tid & 31;
    const int row0 = blockIdx.y * BM;   // batch base
    const int col0 = blockIdx.x * BN;   // packed gate col base
    const int wm = wid & 3;             // 0..3 (M)
    const int wn = wid >> 2;            // 0..3 (N)

    // loader mapping: 512 threads cover 128 rows x 128B (32B per thread)
    const int r     = tid >> 2;
    const int quart = tid & 3;
    const uint32_t rowoff = (uint32_t)r * 128 + (uint32_t)quart * 32;

    // ---- load resident W (9 chunks, 147KB) ----
    {
        const size_t bb = (size_t)(col0 + r) * KTOT + (size_t)quart * 16;
        for (int sub = 0; sub < 9; ++sub) {
            uint32_t dst = sbase + SOFF_BH + sub * 16384;
#pragma unroll
            for (int c = 0; c < 2; ++c)
                cp16(dst + SWZ(rowoff + c * 16), g_Bh + bb + sub * KTILE + c * 8);
        }
        cp_commit();
    }

    // ---- per-thread epilogue constants: c state + bias in registers ----
    const int q  = lane & 3;
    const bool ev = (q & 1) == 0;
    float creg[2][4][2];
    float bb0[4], bb1[4];
#pragma unroll
    for (int nf = 0; nf < 4; ++nf) {
        int cb = wn * 32 + nf * 8 + q * 2;
        bb0[nf] = g_bias[col0 + cb];
        bb1[nf] = g_bias[col0 + cb + 1];
#pragma unroll
        for (int mf = 0; mf < 2; ++mf)
#pragma unroll
            for (int rs = 0; rs < 2; ++rs) {
                int n = (col0 + cb) >> 2;
                int b = row0 + wm * 32 + (lane >> 2) + mf * 16 + rs * 8;
                creg[mf][nf][rs] = c0g[(size_t)b * HID + n];
            }
    }

    // fragment addressing constants
    const int lane7 = lane & 7;
    const int arow  = wm * 32 + ((lane >> 3) & 1) * 8 + lane7;   // + mf*16
    const int ach   = (lane >> 4) & 1;
    const int brow  = wn * 32 + ((lane >> 4) & 1) * 8 + lane7;   // + p*16
    const int bch   = (lane >> 3) & 1;

    const uint32_t sA0 = sbase + SOFF_A;

    // job j = K-chunk j: A(j) x B[j] (resident). A buffer = j % 3 (triple).
    auto issue_job = [&](int jid, int t, int buf) {
        const __half* __restrict__ Asrc;
        size_t abase;
        if (jid == 0) {   // x part (h-independent)
            Asrc  = g_x;
            abase = (size_t)(row0 + r) * XCOLS + (size_t)t * INSZ;
        } else {
            Asrc  = g_h[buf];
            abase = (size_t)(row0 + r) * HID + (size_t)(jid - 1) * KTILE;
        }
        abase += (size_t)quart * 16;
        const uint32_t ao = (uint32_t)(jid % 3) * 16384;
#pragma unroll
        for (int c = 0; c < 2; ++c)
            cp16(sA0 + ao + SWZ(rowoff + c * 16), Asrc + abase + c * 8);
        cp_commit();
    };

    float acc[2][4][4];

    // MMA of one job: 4 kk slices against resident W chunk j
    auto mma_job = [&](int j) {
        const uint32_t sA  = sA0 + (uint32_t)(j % 3) * 16384;
        const uint32_t sBH = sbase + SOFF_BH + (uint32_t)j * 16384;
#pragma unroll
        for (int kk = 0; kk < 4; ++kk) {
            uint32_t af[2][4];
#pragma unroll
            for (int mf = 0; mf < 2; ++mf)
                ldsm4(af[mf], sA + SWZ((uint32_t)(arow + mf * 16) * 128
                                       + (uint32_t)(kk * 2 + ach) * 16));
            uint32_t bf[4][2];
#pragma unroll
            for (int p = 0; p < 2; ++p) {
                uint32_t rr[4];
                ldsm4(rr, sBH + SWZ((uint32_t)(brow + p * 16) * 128
                                    + (uint32_t)(kk * 2 + bch) * 16));
                bf[p * 2 + 0][0] = rr[0]; bf[p * 2 + 0][1] = rr[1];
                bf[p * 2 + 1][0] = rr[2]; bf[p * 2 + 1][1] = rr[3];
            }
#pragma unroll
            for (int mf = 0; mf < 2; ++mf)
#pragma unroll
                for (int nf = 0; nf < 4; ++nf)
                    mma16816(acc[mf][nf], af[mf], bf[nf]);
        }
    };

    // prologue: x job of step 0 (after W group)
    issue_job(0, 0, 0);

    for (int t = 0; t < TSTEPS; ++t) {
        const int buf  = t & 1;
        const int nbuf = buf ^ 1;

        // acc starts at bias (saves the bias add in the epilogue)
#pragma unroll
        for (int mf = 0; mf < 2; ++mf)
#pragma unroll
            for (int nf = 0; nf < 4; ++nf)
#pragma unroll
                for (int rs = 0; rs < 2; ++rs) {
                    acc[mf][nf][rs * 2 + 0] = bb0[nf];
                    acc[mf][nf][rs * 2 + 1] = bb1[nf];
                }

        // ---- job 0 (x): barrier-independent, hides the row-group spin ----
        cp_wait<0>();           // x tile (and W group at t=0) resident
        __syncthreads();
        mma_job(0);

        // ---- row-group barrier: h[t] visible (overlapped by job-0 MMA) ----
        if (t > 0 && tid == 0) {
            const unsigned long long target =
                (unsigned long long)t * (unsigned long long)NROWCTA;
            unsigned long long cur;
            unsigned long long* p = &g_row_ticket[blockIdx.y * 16];
            do {
                asm volatile("ld.acquire.gpu.u64 %0, [%1];" : "=l"(cur) : "l"(p));
            } while (cur < target);
        }
        __syncthreads();   // orders job-0 MMA before h reads / buffer reuse

        // h now safe to read: prime lookahead of 2
        issue_job(1, t, buf);
        issue_job(2, t, buf);

        // ---- jobs 1..8: lookahead-2 pipeline ----
        for (int j = 1; j < NJOBS; ++j) {
            cp_wait<1>();       // job j's group arrived (<=1 pending: j+1 or x)
            __syncthreads();
            if (j + 2 < NJOBS) {
                issue_job(j + 2, t, buf);
            } else if (j + 2 == NJOBS) {
                // j == 7: pre-issue next step's x job (or empty group to keep
                // the wait-depth invariant on the final step)
                if (t + 1 < TSTEPS) issue_job(0, t + 1, nbuf);
                else                cp_commit();
            }
            mma_job(j);
        }

        // ---- fused LSTM epilogue (hw tanh) ----
#pragma unroll
        for (int mf = 0; mf < 2; ++mf) {
#pragma unroll
            for (int nf = 0; nf < 4; ++nf) {
                const int cb = wn * 32 + nf * 8 + q * 2;
#pragma unroll
                for (int rs = 0; rs < 2; ++rs) {
                    float v0 = acc[mf][nf][rs * 2 + 0];
                    float v1 = acc[mf][nf][rs * 2 + 1];
                    // even lanes: x0=sig(i), x1=sig(f); odd: x0=tanh(g), x1=sig(o)
                    float x0 = ev ? fsig(v0) : ftanh(v0);
                    float x1 = fsig(v1);
                    float y0 = __shfl_xor_sync(0xffffffffu, x0, 1);
                    float y1 = __shfl_xor_sync(0xffffffffu, x1, 1);
                    if (ev) {
                        const int n = (col0 + cb) >> 2;
                        const int b = row0 + wm * 32 + (lane >> 2) + mf * 16 + rs * 8;
                        const size_t idx = (size_t)b * HID + n;
                        float cn = x1 * creg[mf][nf][rs] + x0 * y0;   // f*c + i*g
                        creg[mf][nf][rs] = cn;
                        float hn = y1 * ftanh(cn);                    // o * tanh(c)
                        g_h[nbuf][idx] = __float2half_rn(hn);
                    }
                }
            }
        }

        // post arrival for next step's row barrier (release semantics)
        if (t + 1 < TSTEPS) {
            __syncthreads();   // h stores complete block-wide
            if (tid == 0) {
                unsigned long long one = 1ULL;
                asm volatile("red.release.gpu.global.add.u64 [%0], %1;"
                             :: "l"(&g_row_ticket[blockIdx.y * 16]), "l"(one)
                             : "memory");
            }
        }
    }
}

// ---------------- final linear ----------------
__global__ void final_linear_kernel(const float* __restrict__ W_lin,
                                    const float* __restrict__ b_lin,
                                    float* __restrict__ out, int buf)
{
    int b = blockIdx.x;
    int w = threadIdx.y;      // 0..9
    int lane = threadIdx.x;   // 0..31
    const __half* h = g_h[buf] + (size_t)b * HID;
    const float* wl = W_lin + (size_t)w * HID;
    float s = 0.f;
#pragma unroll 4
    for (int k = lane; k < HID; k += 32)
        s += __half2float(h[k]) * wl[k];
#pragma unroll
    for (int off = 16; off; off >>= 1)
        s += __shfl_down_sync(0xffffffffu, s, off);
    if (lane == 0)
        out[b * 10 + w] = s + b_lin[w];
}

// ---------------- launch ----------------
extern "C" void kernel_launch(void* const* d_in, const int* in_sizes, int n_in,
                              void* d_out, int out_size)
{
    const float* x     = (const float*)d_in[0];
    const float* h0    = (const float*)d_in[1];
    const float* c0    = (const float*)d_in[2];
    const float* W_ih  = (const float*)d_in[3];
    const float* W_hh  = (const float*)d_in[4];
    const float* b_ih  = (const float*)d_in[5];
    const float* b_hh  = (const float*)d_in[6];
    const float* W_lin = (const float*)d_in[7];
    const float* b_lin = (const float*)d_in[8];
    float* out = (float*)d_out;

    cudaFuncSetAttribute(lstm_persistent,
                         cudaFuncAttributeMaxDynamicSharedMemorySize, SMEM_TOTAL);

    prepack_x_kernel<<<2048, 256>>>(x);
    prepack_w_kernel<<<1024, 256>>>(W_ih, W_hh, b_ih, b_hh);
    init_state_kernel<<<512, 512>>>(h0);

    dim3 grid(GATES / BN, B_SZ / BM);   // 16 x 8 = 128 CTAs (all resident)
    lstm_persistent<<<grid, 512, SMEM_TOTAL>>>(c0);

    // 256 steps -> final h is in buffer 0
    final_linear_kernel<<<B_SZ, dim3(32, 10)>>>(W_lin, b_lin, out, 0);
}

// round 16
// speedup vs baseline: 1.3766x; 1.0079x over previous
#include <cuda_runtime.h>
#include <cuda_fp16.h>
#include <math.h>
#include <stdint.h>

// ---------------- problem constants ----------------
#define B_SZ   1024
#define HID    512
#define INSZ   64
#define TSTEPS 256
#define GATES  2048              // 4*HID
#define KTOT   576               // INSZ + HID
#define XCOLS  (TSTEPS * INSZ)   // 16384

// ---------------- GEMM tiling ----------------
#define BM 128
#define BN 128
#define KTILE 64                 // 64 fp16 = 128 bytes per row
#define NJOBS 9                  // job j = K-chunk j (0 = x, 1..8 = h)
#define NROWCTA 16               // CTAs per row group (same blockIdx.y)
#define ARRIVALS_PER_STEP 256    // 16 CTAs x 16 warps

// SW128 swizzle (Swizzle<3,4,3>) on byte offsets within a tile
#define SWZ(o) ((o) ^ (((o) >> 3) & 0x70))

// dynamic smem layout (all tile bases 1024-aligned)
#define SOFF_BH    0                         // 9 x 16384 = 147456 (resident W)
#define SOFF_A     147456                    // 3 x 16384 (triple buffer)
#define SOFF_MBAR  (147456 + 49152)          // full/empty pairs, 16B per buffer
#define SMEM_TOTAL (SOFF_MBAR + 64)          // 196672

// ---------------- device scratch (no allocs allowed) ----------------
static __device__ __align__(256) __half g_x[(size_t)B_SZ * XCOLS];   // fp16 x
static __device__ __align__(256) __half g_Bh[GATES * KTOT];          // fp16(W), packed col = n*4+g
static __device__ float  g_bias[GATES];
static __device__ __align__(256) __half g_h[2][B_SZ * HID];          // fp16 h (double buffer)
// per-row-group tickets, 128B apart; reset to 0 at the start of every launch
static __device__ unsigned long long g_row_ticket[8 * 16];

// ---------------- PTX helpers ----------------
__device__ __forceinline__ uint32_t smem_u32(const void* p) {
    uint32_t a;
    asm("{ .reg .u64 t; cvta.to.shared.u64 t, %1; cvt.u32.u64 %0, t; }"
        : "=r"(a) : "l"(p));
    return a;
}

__device__ __forceinline__ void cp16(uint32_t dst, const void* src) {
    asm volatile("cp.async.cg.shared.global [%0], [%1], 16;"
                 :: "r"(dst), "l"(src));
}

// mbarrier ops (sm_80+/90 PTX — NOT tcgen05, safe under compute_103)
__device__ __forceinline__ void mbar_init(uint32_t addr, uint32_t cnt) {
    asm volatile("mbarrier.init.shared.b64 [%0], %1;" :: "r"(addr), "r"(cnt) : "memory");
}
__device__ __forceinline__ void mbar_arrive(uint32_t addr) {
    asm volatile("mbarrier.arrive.shared.b64 _, [%0];" :: "r"(addr) : "memory");
}
// arrive on mbar when all of this thread's prior cp.asyncs have completed
__device__ __forceinline__ void cp_async_arrive(uint32_t addr) {
    asm volatile("cp.async.mbarrier.arrive.noinc.shared.b64 [%0];" :: "r"(addr) : "memory");
}
__device__ __forceinline__ void mwait(uint32_t addr, int parity) {
    asm volatile(
        "{ .reg .pred P;\n"
        "W_%=:\n"
        "mbarrier.try_wait.parity.acquire.cta.shared::cta.b64 P, [%0], %1, 0x989680;\n"
        "@P bra.uni D_%=;\n"
        "bra.uni W_%=;\n"
        "D_%=:\n}"
        :: "r"(addr), "r"(parity) : "memory");
}

__device__ __forceinline__ void ldsm4(uint32_t* r, uint32_t addr) {
    asm volatile("ldmatrix.sync.aligned.m8n8.x4.shared.b16 {%0,%1,%2,%3}, [%4];"
                 : "=r"(r[0]), "=r"(r[1]), "=r"(r[2]), "=r"(r[3]) : "r"(addr));
}

__device__ __forceinline__ void mma16816(float* c, const uint32_t* a, const uint32_t* b) {
    asm volatile(
        "mma.sync.aligned.m16n8k16.row.col.f32.f16.f16.f32 "
        "{%0,%1,%2,%3}, {%4,%5,%6,%7}, {%8,%9}, {%0,%1,%2,%3};"
        : "+f"(c[0]), "+f"(c[1]), "+f"(c[2]), "+f"(c[3])
        : "r"(a[0]), "r"(a[1]), "r"(a[2]), "r"(a[3]), "r"(b[0]), "r"(b[1]));
}

// hardware tanh (sm_75+): 1 MUFU op, |err| ~ 5e-4
__device__ __forceinline__ float ftanh(float x) {
    float y;
    asm("tanh.approx.f32 %0, %1;" : "=f"(y) : "f"(x));
    return y;
}
// sigmoid via hw tanh: sig(x) = 0.5 + 0.5*tanh(x/2)
__device__ __forceinline__ float fsig(float x) {
    return fmaf(0.5f, ftanh(0.5f * x), 0.5f);
}

// ---------------- prepack kernels ----------------
__global__ void prepack_x_kernel(const float* __restrict__ x) {
    size_t idx = (size_t)blockIdx.x * blockDim.x + threadIdx.x;
    size_t stride = (size_t)gridDim.x * blockDim.x;
    const size_t total = (size_t)B_SZ * XCOLS;
    for (size_t i = idx; i < total; i += stride)
        g_x[i] = __float2half_rn(x[i]);
}

__global__ void prepack_w_kernel(const float* __restrict__ W_ih,
                                 const float* __restrict__ W_hh,
                                 const float* __restrict__ b_ih,
                                 const float* __restrict__ b_hh) {
    int idx = blockIdx.x * blockDim.x + threadIdx.x;
    int stride = gridDim.x * blockDim.x;
    const int total = GATES * KTOT;
    for (int i = idx; i < total; i += stride) {
        int col = i / KTOT;
        int k   = i - col * KTOT;
        int n = col >> 2, g = col & 3;
        int row = g * HID + n;
        float v = (k < INSZ) ? W_ih[row * INSZ + k] : W_hh[row * HID + (k - INSZ)];
        g_Bh[i] = __float2half_rn(v);
    }
    for (int i = idx; i < GATES; i += stride) {
        int n = i >> 2, g = i & 3;
        int row = g * HID + n;
        g_bias[i] = b_ih[row] + b_hh[row];
    }
}

// init h0 (fp16) + reset row tickets
__global__ void init_state_kernel(const float* __restrict__ h0) {
    int idx = blockIdx.x * blockDim.x + threadIdx.x;
    int stride = gridDim.x * blockDim.x;
    for (int i = idx; i < B_SZ * HID; i += stride)
        g_h[0][i] = __float2half_rn(h0[i]);
    if (blockIdx.x == 0 && threadIdx.x < 8 * 16)
        g_row_ticket[threadIdx.x] = 0ULL;
}

// ---------------- persistent LSTM kernel (512 threads) ----------------
// mbarrier producer/consumer pipeline over a 3-deep A ring:
//   job jid -> buffer jid % 3 (9 jobs/step keeps the map step-invariant)
//   full[b]  : count 512, cp.async completion arrivals (all threads)
//   empty[b] : count 16, one arrival per warp after its MMA of that buffer
// No __syncthreads in the steady state; inter-CTA sync via per-warp
// release-arrivals on the row-group ticket (256 arrivals per step).
__global__ __launch_bounds__(512, 1)
void lstm_persistent(const float* __restrict__ c0g)
{
    extern __shared__ char smem[];
    const uint32_t sbase = smem_u32(smem);
    const int tid  = threadIdx.x;
    const int wid  = tid >> 5;
    const int lane = tid & 31;
    const int row0 = blockIdx.y * BM;   // batch base
    const int col0 = blockIdx.x * BN;   // packed gate col base
    const int wm = wid & 3;             // 0..3 (M)
    const int wn = wid >> 2;            // 0..3 (N)

    const uint32_t mb = sbase + SOFF_MBAR;
    // full[b] at mb + b*16, empty[b] at mb + b*16 + 8
    if (tid == 0) {
#pragma unroll
        for (int b = 0; b < 3; ++b) {
            mbar_init(mb + b * 16,     512);
            mbar_init(mb + b * 16 + 8, 16);
        }
    }

    // loader mapping: 512 threads cover 128 rows x 128B (32B per thread)
    const int r     = tid >> 2;
    const int quart = tid & 3;
    const uint32_t rowoff = (uint32_t)r * 128 + (uint32_t)quart * 32;

    // ---- issue resident W loads (completion tracked by the first full-arrive) ----
    {
        const size_t bb = (size_t)(col0 + r) * KTOT + (size_t)quart * 16;
        for (int sub = 0; sub < 9; ++sub) {
            uint32_t dst = sbase + SOFF_BH + sub * 16384;
#pragma unroll
            for (int c = 0; c < 2; ++c)
                cp16(dst + SWZ(rowoff + c * 16), g_Bh + bb + sub * KTILE + c * 8);
        }
    }

    // ---- per-thread epilogue constants: c state + bias in registers ----
    const int q  = lane & 3;
    const bool ev = (q & 1) == 0;
    float creg[2][4][2];
    float bb0[4], bb1[4];
#pragma unroll
    for (int nf = 0; nf < 4; ++nf) {
        int cb = wn * 32 + nf * 8 + q * 2;
        bb0[nf] = g_bias[col0 + cb];
        bb1[nf] = g_bias[col0 + cb + 1];
#pragma unroll
        for (int mf = 0; mf < 2; ++mf)
#pragma unroll
            for (int rs = 0; rs < 2; ++rs) {
                int n = (col0 + cb) >> 2;
                int b = row0 + wm * 32 + (lane >> 2) + mf * 16 + rs * 8;
                creg[mf][nf][rs] = c0g[(size_t)b * HID + n];
            }
    }

    __syncthreads();   // mbarrier init visible before any arrive/wait

    // fragment addressing constants
    const int lane7 = lane & 7;
    const int arow  = wm * 32 + ((lane >> 3) & 1) * 8 + lane7;   // + mf*16
    const int ach   = (lane >> 4) & 1;
    const int brow  = wn * 32 + ((lane >> 4) & 1) * 8 + lane7;   // + p*16
    const int bch   = (lane >> 3) & 1;

    const uint32_t sA0 = sbase + SOFF_A;

    auto issue_x = [&](int t) {   // x -> buffer 0
        const size_t abase = (size_t)(row0 + r) * XCOLS + (size_t)t * INSZ
                             + (size_t)quart * 16;
#pragma unroll
        for (int c = 0; c < 2; ++c)
            cp16(sA0 + SWZ(rowoff + c * 16), g_x + abase + c * 8);
    };
    auto issue_h = [&](int jid, int buf) {   // h chunk jid -> buffer jid%3
        const size_t abase = (size_t)(row0 + r) * HID + (size_t)(jid - 1) * KTILE
                             + (size_t)quart * 16;
        const uint32_t ao = (uint32_t)(jid % 3) * 16384;
#pragma unroll
        for (int c = 0; c < 2; ++c)
            cp16(sA0 + ao + SWZ(rowoff + c * 16), g_h[buf] + abase + c * 8);
    };

    float acc[2][4][4];

    auto mma_job = [&](int j) {
        const uint32_t sA  = sA0 + (uint32_t)(j % 3) * 16384;
        const uint32_t sBH = sbase + SOFF_BH + (uint32_t)j * 16384;
#pragma unroll
        for (int kk = 0; kk < 4; ++kk) {
            uint32_t af[2][4];
#pragma unroll
            for (int mf = 0; mf < 2; ++mf)
                ldsm4(af[mf], sA + SWZ((uint32_t)(arow + mf * 16) * 128
                                       + (uint32_t)(kk * 2 + ach) * 16));
            uint32_t bf[4][2];
#pragma unroll
            for (int p = 0; p < 2; ++p) {
                uint32_t rr[4];
                ldsm4(rr, sBH + SWZ((uint32_t)(brow + p * 16) * 128
                                    + (uint32_t)(kk * 2 + bch) * 16));
                bf[p * 2 + 0][0] = rr[0]; bf[p * 2 + 0][1] = rr[1];
                bf[p * 2 + 1][0] = rr[2]; bf[p * 2 + 1][1] = rr[3];
            }
#pragma unroll
            for (int mf = 0; mf < 2; ++mf)
#pragma unroll
                for (int nf = 0; nf < 4; ++nf)
                    mma16816(acc[mf][nf], af[mf], bf[nf]);
        }
    };

    // pipeline parities: consumer(full) starts 0, producer(empty) starts 1
    int pf[3] = {0, 0, 0};
    int pe[3] = {1, 1, 1};

    // prologue: produce x(0) into buffer 0
    mwait(mb + 0 * 16 + 8, pe[0]); pe[0] ^= 1;   // fresh barrier: passes
    issue_x(0);
    cp_async_arrive(mb + 0 * 16);                // also covers the W loads

    for (int t = 0; t < TSTEPS; ++t) {
        const int buf  = t & 1;
        const int nbuf = buf ^ 1;

        // acc starts at bias
#pragma unroll
        for (int mf = 0; mf < 2; ++mf)
#pragma unroll
            for (int nf = 0; nf < 4; ++nf)
#pragma unroll
                for (int rs = 0; rs < 2; ++rs) {
                    acc[mf][nf][rs * 2 + 0] = bb0[nf];
                    acc[mf][nf][rs * 2 + 1] = bb1[nf];
                }

        // ---- consume job 0 (x) — barrier-independent ----
        mwait(mb + 0 * 16, pf[0]); pf[0] ^= 1;
        mma_job(0);
        __syncwarp();
        if (lane == 0) mbar_arrive(mb + 0 * 16 + 8);

        // ---- row-group ticket: h[t] visible (per-thread acquire spin) ----
        if (t > 0) {
            const unsigned long long target =
                (unsigned long long)t * (unsigned long long)ARRIVALS_PER_STEP;
            unsigned long long cur;
            unsigned long long* p = &g_row_ticket[blockIdx.y * 16];
            do {
                asm volatile("ld.acquire.gpu.u64 %0, [%1];" : "=l"(cur) : "l"(p));
            } while (cur < target);
        }

        // ---- produce jobs 1, 2 ----
        mwait(mb + 1 * 16 + 8, pe[1]); pe[1] ^= 1;
        issue_h(1, buf);
        cp_async_arrive(mb + 1 * 16);
        mwait(mb + 2 * 16 + 8, pe[2]); pe[2] ^= 1;
        issue_h(2, buf);
        cp_async_arrive(mb + 2 * 16);

        // ---- jobs 1..8: decoupled pipeline ----
#pragma unroll
        for (int j = 1; j < NJOBS; ++j) {
            const int b = j % 3;
            mwait(mb + b * 16, pf[b]); pf[b] ^= 1;
            if (j + 2 < NJOBS) {
                const int b2 = (j + 2) % 3;
                mwait(mb + b2 * 16 + 8, pe[b2]); pe[b2] ^= 1;
                issue_h(j + 2, buf);
                cp_async_arrive(mb + b2 * 16);
            } else if (j == NJOBS - 2) {   // j == 7: pre-produce next x into buf 0
                if (t + 1 < TSTEPS) {
                    mwait(mb + 0 * 16 + 8, pe[0]); pe[0] ^= 1;
                    issue_x(t + 1);
                    cp_async_arrive(mb + 0 * 16);
                }
            }
            mma_job(j);
            __syncwarp();
            if (lane == 0) mbar_arrive(mb + b * 16 + 8);
        }

        // ---- fused LSTM epilogue (hw tanh) ----
#pragma unroll
        for (int mf = 0; mf < 2; ++mf) {
#pragma unroll
            for (int nf = 0; nf < 4; ++nf) {
                const int cb = wn * 32 + nf * 8 + q * 2;
#pragma unroll
                for (int rs = 0; rs < 2; ++rs) {
                    float v0 = acc[mf][nf][rs * 2 + 0];
                    float v1 = acc[mf][nf][rs * 2 + 1];
                    // even lanes: x0=sig(i), x1=sig(f); odd: x0=tanh(g), x1=sig(o)
                    float x0 = ev ? fsig(v0) : ftanh(v0);
                    float x1 = fsig(v1);
                    float y0 = __shfl_xor_sync(0xffffffffu, x0, 1);
                    float y1 = __shfl_xor_sync(0xffffffffu, x1, 1);
                    if (ev) {
                        const int n = (col0 + cb) >> 2;
                        const int b = row0 + wm * 32 + (lane >> 2) + mf * 16 + rs * 8;
                        const size_t idx = (size_t)b * HID + n;
                        float cn = x1 * creg[mf][nf][rs] + x0 * y0;   // f*c + i*g
                        creg[mf][nf][rs] = cn;
                        float hn = y1 * ftanh(cn);                    // o * tanh(c)
                        g_h[nbuf][idx] = __float2half_rn(hn);
                    }
                }
            }
        }

        // per-warp release arrival on the row ticket (no block barrier)
        if (t + 1 < TSTEPS) {
            __syncwarp();    // warp lanes' h stores ordered before the arrive
            if (lane == 0) {
                unsigned long long one = 1ULL;
                asm volatile("red.release.gpu.global.add.u64 [%0], %1;"
                             :: "l"(&g_row_ticket[blockIdx.y * 16]), "l"(one)
                             : "memory");
            }
        }
    }
}

// ---------------- final linear ----------------
__global__ void final_linear_kernel(const float* __restrict__ W_lin,
                                    const float* __restrict__ b_lin,
                                    float* __restrict__ out, int buf)
{
    int b = blockIdx.x;
    int w = threadIdx.y;      // 0..9
    int lane = threadIdx.x;   // 0..31
    const __half* h = g_h[buf] + (size_t)b * HID;
    const float* wl = W_lin + (size_t)w * HID;
    float s = 0.f;
#pragma unroll 4
    for (int k = lane; k < HID; k += 32)
        s += __half2float(h[k]) * wl[k];
#pragma unroll
    for (int off = 16; off; off >>= 1)
        s += __shfl_down_sync(0xffffffffu, s, off);
    if (lane == 0)
        out[b * 10 + w] = s + b_lin[w];
}

// ---------------- launch ----------------
extern "C" void kernel_launch(void* const* d_in, const int* in_sizes, int n_in,
                              void* d_out, int out_size)
{
    const float* x     = (const float*)d_in[0];
    const float* h0    = (const float*)d_in[1];
    const float* c0    = (const float*)d_in[2];
    const float* W_ih  = (const float*)d_in[3];
    const float* W_hh  = (const float*)d_in[4];
    const float* b_ih  = (const float*)d_in[5];
    const float* b_hh  = (const float*)d_in[6];
    const float* W_lin = (const float*)d_in[7];
    const float* b_lin = (const float*)d_in[8];
    float* out = (float*)d_out;

    cudaFuncSetAttribute(lstm_persistent,
                         cudaFuncAttributeMaxDynamicSharedMemorySize, SMEM_TOTAL);

    prepack_x_kernel<<<2048, 256>>>(x);
    prepack_w_kernel<<<1024, 256>>>(W_ih, W_hh, b_ih, b_hh);
    init_state_kernel<<<512, 512>>>(h0);

    dim3 grid(GATES / BN, B_SZ / BM);   // 16 x 8 = 128 CTAs (all resident)
    lstm_persistent<<<grid, 512, SMEM_TOTAL>>>(c0);

    // 256 steps -> final h is in buffer 0
    final_linear_kernel<<<B_SZ, dim3(32, 10)>>>(W_lin, b_lin, out, 0);
}

// round 17
// speedup vs baseline: 1.5311x; 1.1123x over previous
#include <cuda_runtime.h>
#include <cuda_fp16.h>
#include <math.h>
#include <stdint.h>

// ---------------- problem constants ----------------
#define B_SZ   1024
#define HID    512
#define INSZ   64
#define TSTEPS 256
#define GATES  2048              // 4*HID
#define KTOT   576               // INSZ + HID
#define XCOLS  (TSTEPS * INSZ)   // 16384

// ---------------- GEMM tiling ----------------
#define BM 128
#define BN 128
#define KTILE 64                 // 64 fp16 = 128 bytes per row
#define NJOBS 9                  // job j = K-chunk j (0 = x, 1..8 = h)
#define NROWCTA 16               // CTAs per row group (same blockIdx.y)
#define ARRIVALS_PER_STEP 256    // 16 CTAs x 16 warps

// SW128 swizzle (Swizzle<3,4,3>) on byte offsets within a tile
#define SWZ(o) ((o) ^ (((o) >> 3) & 0x70))

// dynamic smem layout (all tile bases 1024-aligned)
#define SOFF_BH    0                         // 9 x 16384 = 147456 (resident W)
#define SOFF_A     147456                    // 3 x 16384 (triple buffer)
#define SOFF_MBAR  (147456 + 49152)          // full/empty pairs, 16B per buffer
#define SMEM_TOTAL (SOFF_MBAR + 64)          // 196672

// ---------------- device scratch (no allocs allowed) ----------------
static __device__ __align__(256) __half g_x[(size_t)B_SZ * XCOLS];   // fp16 x
static __device__ __align__(256) __half g_Bh[GATES * KTOT];          // fp16(W), packed col = n*4+g
static __device__ float  g_bias[GATES];
static __device__ __align__(256) __half g_h[2][B_SZ * HID];          // fp16 h (double buffer)
// per-row-group tickets, 128B apart; reset to 0 at the start of every launch
static __device__ unsigned long long g_row_ticket[8 * 16];

// ---------------- PTX helpers ----------------
__device__ __forceinline__ uint32_t smem_u32(const void* p) {
    uint32_t a;
    asm("{ .reg .u64 t; cvta.to.shared.u64 t, %1; cvt.u32.u64 %0, t; }"
        : "=r"(a) : "l"(p));
    return a;
}

__device__ __forceinline__ void cp16(uint32_t dst, const void* src) {
    asm volatile("cp.async.cg.shared.global [%0], [%1], 16;"
                 :: "r"(dst), "l"(src));
}

// mbarrier ops (sm_80+/90 PTX — NOT tcgen05, safe under compute_103)
__device__ __forceinline__ void mbar_init(uint32_t addr, uint32_t cnt) {
    asm volatile("mbarrier.init.shared.b64 [%0], %1;" :: "r"(addr), "r"(cnt) : "memory");
}
__device__ __forceinline__ void mbar_arrive(uint32_t addr) {
    asm volatile("mbarrier.arrive.shared.b64 _, [%0];" :: "r"(addr) : "memory");
}
// arrive on mbar when all of this thread's prior cp.asyncs have completed
__device__ __forceinline__ void cp_async_arrive(uint32_t addr) {
    asm volatile("cp.async.mbarrier.arrive.noinc.shared.b64 [%0];" :: "r"(addr) : "memory");
}
__device__ __forceinline__ void mwait(uint32_t addr, int parity) {
    asm volatile(
        "{ .reg .pred P;\n"
        "W_%=:\n"
        "mbarrier.try_wait.parity.acquire.cta.shared::cta.b64 P, [%0], %1, 0x989680;\n"
        "@P bra.uni D_%=;\n"
        "bra.uni W_%=;\n"
        "D_%=:\n}"
        :: "r"(addr), "r"(parity) : "memory");
}

__device__ __forceinline__ void ldsm4(uint32_t* r, uint32_t addr) {
    asm volatile("ldmatrix.sync.aligned.m8n8.x4.shared.b16 {%0,%1,%2,%3}, [%4];"
                 : "=r"(r[0]), "=r"(r[1]), "=r"(r[2]), "=r"(r[3]) : "r"(addr));
}

__device__ __forceinline__ void mma16816(float* c, const uint32_t* a, const uint32_t* b) {
    asm volatile(
        "mma.sync.aligned.m16n8k16.row.col.f32.f16.f16.f32 "
        "{%0,%1,%2,%3}, {%4,%5,%6,%7}, {%8,%9}, {%0,%1,%2,%3};"
        : "+f"(c[0]), "+f"(c[1]), "+f"(c[2]), "+f"(c[3])
        : "r"(a[0]), "r"(a[1]), "r"(a[2]), "r"(a[3]), "r"(b[0]), "r"(b[1]));
}

// hardware tanh (sm_75+): 1 MUFU op, |err| ~ 5e-4
__device__ __forceinline__ float ftanh(float x) {
    float y;
    asm("tanh.approx.f32 %0, %1;" : "=f"(y) : "f"(x));
    return y;
}
// sigmoid via hw tanh: sig(x) = 0.5 + 0.5*tanh(x/2)
__device__ __forceinline__ float fsig(float x) {
    return fmaf(0.5f, ftanh(0.5f * x), 0.5f);
}

// ---------------- prepack kernels ----------------
__global__ void prepack_x_kernel(const float* __restrict__ x) {
    size_t idx = (size_t)blockIdx.x * blockDim.x + threadIdx.x;
    size_t stride = (size_t)gridDim.x * blockDim.x;
    const size_t total = (size_t)B_SZ * XCOLS;
    for (size_t i = idx; i < total; i += stride)
        g_x[i] = __float2half_rn(x[i]);
}

__global__ void prepack_w_kernel(const float* __restrict__ W_ih,
                                 const float* __restrict__ W_hh,
                                 const float* __restrict__ b_ih,
                                 const float* __restrict__ b_hh) {
    int idx = blockIdx.x * blockDim.x + threadIdx.x;
    int stride = gridDim.x * blockDim.x;
    const int total = GATES * KTOT;
    for (int i = idx; i < total; i += stride) {
        int col = i / KTOT;
        int k   = i - col * KTOT;
        int n = col >> 2, g = col & 3;
        int row = g * HID + n;
        float v = (k < INSZ) ? W_ih[row * INSZ + k] : W_hh[row * HID + (k - INSZ)];
        g_Bh[i] = __float2half_rn(v);
    }
    for (int i = idx; i < GATES; i += stride) {
        int n = i >> 2, g = i & 3;
        int row = g * HID + n;
        g_bias[i] = b_ih[row] + b_hh[row];
    }
}

// init h0 (fp16) + reset row tickets
__global__ void init_state_kernel(const float* __restrict__ h0) {
    int idx = blockIdx.x * blockDim.x + threadIdx.x;
    int stride = gridDim.x * blockDim.x;
    for (int i = idx; i < B_SZ * HID; i += stride)
        g_h[0][i] = __float2half_rn(h0[i]);
    if (blockIdx.x == 0 && threadIdx.x < 8 * 16)
        g_row_ticket[threadIdx.x] = 0ULL;
}

// ---------------- persistent LSTM kernel (512 threads) ----------------
// mbarrier producer/consumer pipeline over a 3-deep A ring (as R16), plus
// warp-shuffle-packed h stores: one 16B st.global.v4 per (mf,rs) per q==0
// lane instead of 16 scattered 2B stores per thread.
__global__ __launch_bounds__(512, 1)
void lstm_persistent(const float* __restrict__ c0g)
{
    extern __shared__ char smem[];
    const uint32_t sbase = smem_u32(smem);
    const int tid  = threadIdx.x;
    const int wid  = tid >> 5;
    const int lane = tid & 31;
    const int row0 = blockIdx.y * BM;   // batch base
    const int col0 = blockIdx.x * BN;   // packed gate col base
    const int wm = wid & 3;             // 0..3 (M)
    const int wn = wid >> 2;            // 0..3 (N)

    const uint32_t mb = sbase + SOFF_MBAR;
    if (tid == 0) {
#pragma unroll
        for (int b = 0; b < 3; ++b) {
            mbar_init(mb + b * 16,     512);
            mbar_init(mb + b * 16 + 8, 16);
        }
    }

    // loader mapping: 512 threads cover 128 rows x 128B (32B per thread)
    const int r     = tid >> 2;
    const int quart = tid & 3;
    const uint32_t rowoff = (uint32_t)r * 128 + (uint32_t)quart * 32;

    // ---- issue resident W loads (completion tracked by first full-arrive) ----
    {
        const size_t bb = (size_t)(col0 + r) * KTOT + (size_t)quart * 16;
        for (int sub = 0; sub < 9; ++sub) {
            uint32_t dst = sbase + SOFF_BH + sub * 16384;
#pragma unroll
            for (int c = 0; c < 2; ++c)
                cp16(dst + SWZ(rowoff + c * 16), g_Bh + bb + sub * KTILE + c * 8);
        }
    }

    // ---- per-thread epilogue constants: c state + bias in registers ----
    const int q  = lane & 3;
    const bool ev = (q & 1) == 0;
    float creg[2][4][2];
    float bb0[4], bb1[4];
#pragma unroll
    for (int nf = 0; nf < 4; ++nf) {
        int cb = wn * 32 + nf * 8 + q * 2;
        bb0[nf] = g_bias[col0 + cb];
        bb1[nf] = g_bias[col0 + cb + 1];
#pragma unroll
        for (int mf = 0; mf < 2; ++mf)
#pragma unroll
            for (int rs = 0; rs < 2; ++rs) {
                int n = (col0 + cb) >> 2;
                int b = row0 + wm * 32 + (lane >> 2) + mf * 16 + rs * 8;
                creg[mf][nf][rs] = c0g[(size_t)b * HID + n];
            }
    }

    __syncthreads();   // mbarrier init visible before any arrive/wait

    // fragment addressing constants
    const int lane7 = lane & 7;
    const int arow  = wm * 32 + ((lane >> 3) & 1) * 8 + lane7;   // + mf*16
    const int ach   = (lane >> 4) & 1;
    const int brow  = wn * 32 + ((lane >> 4) & 1) * 8 + lane7;   // + p*16
    const int bch   = (lane >> 3) & 1;

    // h store base (q==0 lanes store 8 consecutive n = 16B)
    const int nbase = (col0 >> 2) + wn * 8;

    const uint32_t sA0 = sbase + SOFF_A;

    auto issue_x = [&](int t) {   // x -> buffer 0
        const size_t abase = (size_t)(row0 + r) * XCOLS + (size_t)t * INSZ
                             + (size_t)quart * 16;
#pragma unroll
        for (int c = 0; c < 2; ++c)
            cp16(sA0 + SWZ(rowoff + c * 16), g_x + abase + c * 8);
    };
    auto issue_h = [&](int jid, int buf) {   // h chunk jid -> buffer jid%3
        const size_t abase = (size_t)(row0 + r) * HID + (size_t)(jid - 1) * KTILE
                             + (size_t)quart * 16;
        const uint32_t ao = (uint32_t)(jid % 3) * 16384;
#pragma unroll
        for (int c = 0; c < 2; ++c)
            cp16(sA0 + ao + SWZ(rowoff + c * 16), g_h[buf] + abase + c * 8);
    };

    float acc[2][4][4];

    auto mma_job = [&](int j) {
        const uint32_t sA  = sA0 + (uint32_t)(j % 3) * 16384;
        const uint32_t sBH = sbase + SOFF_BH + (uint32_t)j * 16384;
#pragma unroll
        for (int kk = 0; kk < 4; ++kk) {
            uint32_t af[2][4];
#pragma unroll
            for (int mf = 0; mf < 2; ++mf)
                ldsm4(af[mf], sA + SWZ((uint32_t)(arow + mf * 16) * 128
                                       + (uint32_t)(kk * 2 + ach) * 16));
            uint32_t bf[4][2];
#pragma unroll
            for (int p = 0; p < 2; ++p) {
                uint32_t rr[4];
                ldsm4(rr, sBH + SWZ((uint32_t)(brow + p * 16) * 128
                                    + (uint32_t)(kk * 2 + bch) * 16));
                bf[p * 2 + 0][0] = rr[0]; bf[p * 2 + 0][1] = rr[1];
                bf[p * 2 + 1][0] = rr[2]; bf[p * 2 + 1][1] = rr[3];
            }
#pragma unroll
            for (int mf = 0; mf < 2; ++mf)
#pragma unroll
                for (int nf = 0; nf < 4; ++nf)
                    mma16816(acc[mf][nf], af[mf], bf[nf]);
        }
    };

    // pipeline parities: consumer(full) starts 0, producer(empty) starts 1
    int pf[3] = {0, 0, 0};
    int pe[3] = {1, 1, 1};

    // prologue: produce x(0) into buffer 0
    mwait(mb + 0 * 16 + 8, pe[0]); pe[0] ^= 1;   // fresh barrier: passes
    issue_x(0);
    cp_async_arrive(mb + 0 * 16);                // also covers the W loads

    for (int t = 0; t < TSTEPS; ++t) {
        const int buf  = t & 1;
        const int nbuf = buf ^ 1;

        // acc starts at bias
#pragma unroll
        for (int mf = 0; mf < 2; ++mf)
#pragma unroll
            for (int nf = 0; nf < 4; ++nf)
#pragma unroll
                for (int rs = 0; rs < 2; ++rs) {
                    acc[mf][nf][rs * 2 + 0] = bb0[nf];
                    acc[mf][nf][rs * 2 + 1] = bb1[nf];
                }

        // ---- consume job 0 (x) — barrier-independent ----
        mwait(mb + 0 * 16, pf[0]); pf[0] ^= 1;
        mma_job(0);
        __syncwarp();
        if (lane == 0) mbar_arrive(mb + 0 * 16 + 8);

        // ---- row-group ticket: h[t] visible ----
        if (t > 0) {
            const unsigned long long target =
                (unsigned long long)t * (unsigned long long)ARRIVALS_PER_STEP;
            unsigned long long cur;
            unsigned long long* p = &g_row_ticket[blockIdx.y * 16];
            do {
                asm volatile("ld.acquire.gpu.u64 %0, [%1];" : "=l"(cur) : "l"(p));
            } while (cur < target);
        }

        // ---- produce jobs 1, 2 ----
        mwait(mb + 1 * 16 + 8, pe[1]); pe[1] ^= 1;
        issue_h(1, buf);
        cp_async_arrive(mb + 1 * 16);
        mwait(mb + 2 * 16 + 8, pe[2]); pe[2] ^= 1;
        issue_h(2, buf);
        cp_async_arrive(mb + 2 * 16);

        // ---- jobs 1..8: decoupled pipeline ----
#pragma unroll
        for (int j = 1; j < NJOBS; ++j) {
            const int b = j % 3;
            mwait(mb + b * 16, pf[b]); pf[b] ^= 1;
            if (j + 2 < NJOBS) {
                const int b2 = (j + 2) % 3;
                mwait(mb + b2 * 16 + 8, pe[b2]); pe[b2] ^= 1;
                issue_h(j + 2, buf);
                cp_async_arrive(mb + b2 * 16);
            } else if (j == NJOBS - 2) {   // j == 7: pre-produce next x into buf 0
                if (t + 1 < TSTEPS) {
                    mwait(mb + 0 * 16 + 8, pe[0]); pe[0] ^= 1;
                    issue_x(t + 1);
                    cp_async_arrive(mb + 0 * 16);
                }
            }
            mma_job(j);
            __syncwarp();
            if (lane == 0) mbar_arrive(mb + b * 16 + 8);
        }

        // ---- fused LSTM epilogue (hw tanh, shuffle-packed 16B h stores) ----
#pragma unroll
        for (int mf = 0; mf < 2; ++mf) {
#pragma unroll
            for (int rs = 0; rs < 2; ++rs) {
                uint32_t my01 = 0, my23 = 0;   // packed halves: nf0|nf1, nf2|nf3
#pragma unroll
                for (int nf = 0; nf < 4; ++nf) {
                    float v0 = acc[mf][nf][rs * 2 + 0];
                    float v1 = acc[mf][nf][rs * 2 + 1];
                    // even lanes: x0=sig(i), x1=sig(f); odd: x0=tanh(g), x1=sig(o)
                    float x0 = ev ? fsig(v0) : ftanh(v0);
                    float x1 = fsig(v1);
                    float y0 = __shfl_xor_sync(0xffffffffu, x0, 1);
                    float y1 = __shfl_xor_sync(0xffffffffu, x1, 1);
                    // arithmetic on all lanes; results meaningful on q==0,2
                    float cn = x1 * creg[mf][nf][rs] + x0 * y0;   // f*c + i*g
                    creg[mf][nf][rs] = cn;
                    float hn = y1 * ftanh(cn);                    // o * tanh(c)
                    uint32_t hh = (uint32_t)__half_as_ushort(__float2half_rn(hn));
                    if (nf < 2) my01 |= hh << (nf * 16);
                    else        my23 |= hh << ((nf - 2) * 16);
                }
                // merge q==2 lane's odd-n halves into q==0 lane, store 16B
                uint32_t ot01 = __shfl_down_sync(0xffffffffu, my01, 2);
                uint32_t ot23 = __shfl_down_sync(0xffffffffu, my23, 2);
                if (q == 0) {
                    uint32_t w0 = (my01 & 0xFFFFu) | (ot01 << 16);
                    uint32_t w1 = (my01 >> 16)     | (ot01 & 0xFFFF0000u);
                    uint32_t w2 = (my23 & 0xFFFFu) | (ot23 << 16);
                    uint32_t w3 = (my23 >> 16)     | (ot23 & 0xFFFF0000u);
                    const int b = row0 + wm * 32 + (lane >> 2) + mf * 16 + rs * 8;
                    uint32_t* dst = reinterpret_cast<uint32_t*>(
                        g_h[nbuf] + (size_t)b * HID + nbase);
                    asm volatile("st.global.v4.b32 [%0], {%1, %2, %3, %4};"
                                 :: "l"(dst), "r"(w0), "r"(w1), "r"(w2), "r"(w3)
                                 : "memory");
                }
            }
        }

        // per-warp release arrival on the row ticket
        if (t + 1 < TSTEPS) {
            __syncwarp();    // warp lanes' h stores ordered before the arrive
            if (lane == 0) {
                unsigned long long one = 1ULL;
                asm volatile("red.release.gpu.global.add.u64 [%0], %1;"
                             :: "l"(&g_row_ticket[blockIdx.y * 16]), "l"(one)
                             : "memory");
            }
        }
    }
}

// ---------------- final linear ----------------
__global__ void final_linear_kernel(const float* __restrict__ W_lin,
                                    const float* __restrict__ b_lin,
                                    float* __restrict__ out, int buf)
{
    int b = blockIdx.x;
    int w = threadIdx.y;      // 0..9
    int lane = threadIdx.x;   // 0..31
    const __half* h = g_h[buf] + (size_t)b * HID;
    const float* wl = W_lin + (size_t)w * HID;
    float s = 0.f;
#pragma unroll 4
    for (int k = lane; k < HID; k += 32)
        s += __half2float(h[k]) * wl[k];
#pragma unroll
    for (int off = 16; off; off >>= 1)
        s += __shfl_down_sync(0xffffffffu, s, off);
    if (lane == 0)
        out[b * 10 + w] = s + b_lin[w];
}

// ---------------- launch ----------------
extern "C" void kernel_launch(void* const* d_in, const int* in_sizes, int n_in,
                              void* d_out, int out_size)
{
    const float* x     = (const float*)d_in[0];
    const float* h0    = (const float*)d_in[1];
    const float* c0    = (const float*)d_in[2];
    const float* W_ih  = (const float*)d_in[3];
    const float* W_hh  = (const float*)d_in[4];
    const float* b_ih  = (const float*)d_in[5];
    const float* b_hh  = (const float*)d_in[6];
    const float* W_lin = (const float*)d_in[7];
    const float* b_lin = (const float*)d_in[8];
    float* out = (float*)d_out;

    cudaFuncSetAttribute(lstm_persistent,
                         cudaFuncAttributeMaxDynamicSharedMemorySize, SMEM_TOTAL);

    prepack_x_kernel<<<2048, 256>>>(x);
    prepack_w_kernel<<<1024, 256>>>(W_ih, W_hh, b_ih, b_hh);
    init_state_kernel<<<512, 512>>>(h0);

    dim3 grid(GATES / BN, B_SZ / BM);   // 16 x 8 = 128 CTAs (all resident)
    lstm_persistent<<<grid, 512, SMEM_TOTAL>>>(c0);

    // 256 steps -> final h is in buffer 0
    final_linear_kernel<<<B_SZ, dim3(32, 10)>>>(W_lin, b_lin, out, 0);
}